// round 3
// baseline (speedup 1.0000x reference)
#include <cuda_runtime.h>
#include <cstdint>

// PolyLoss: N=4096 rows, V=128 circular shifts, last dim = 2 (packed f32x2).
// per_shift[n,s] = sum_v |pred[n,(s+v)%V] - gt[n,v]|_1 ; loss = mean_n min_s / V
//
// 2 warps per row (warp half h covers v in [64h, 64h+64)). Thread lane owns
// shifts 4*lane..4*lane+3 via a sliding register window over pred positions.
// Pred entries (ulonglong2 = 2 packed-f32x2 positions) are stored even/odd
// split (sA/sB) so window loads are 16B-contiguous across lanes (no wavefront
// waste). 4 instr per (shift,v) pair: 2 fma-pipe (FFMA2) + 2 alu-pipe (LOP3).

#define NROWS 4096
#define V 128
#define NCTA 2048            // 2 rows per CTA, 4 warps
#define THREADS 128

__device__ float g_partial[NCTA];
__device__ int g_ctr;

__device__ __forceinline__ uint64_t fma2(uint64_t a, uint64_t b, uint64_t c) {
    uint64_t d;
    asm("fma.rn.f32x2 %0, %1, %2, %3;" : "=l"(d) : "l"(a), "l"(b), "l"(c));
    return d;
}

// acc += | p - g |  (componentwise, packed): FFMA2 + 2xLOP3 + FFMA2
#define ACC(p2, g2, acc) do {                      \
    uint64_t _d = fma2((g2), NEG1, (p2));          \
    _d &= 0x7fffffff7fffffffULL;                   \
    (acc) = fma2(_d, ONE1, (acc));                 \
} while (0)

__global__ void __launch_bounds__(THREADS) polyloss_kernel(
    const float* __restrict__ pred, const float* __restrict__ gt,
    float* __restrict__ out)
{
    // Entry e_k = ulonglong2 holding positions (2k, 2k+1), k = 0..131 with
    // e_{k+64} = e_k (circular dup). Even entries in sA, odd in sB:
    // e_{2j} = sA[j], e_{2j+1} = sB[j].
    __shared__ ulonglong2 sA[2][66];
    __shared__ ulonglong2 sB[2][66];
    __shared__ ulonglong2 sg[2][64];
    __shared__ float4 ssum[4][32];
    __shared__ float s_rowmin[2];
    __shared__ int s_is_last;
    __shared__ float s_red[THREADS];

    const int tid  = threadIdx.x;
    const int w    = tid >> 5;
    const int lane = tid & 31;
    const int rl   = w >> 1;     // row within CTA (0,1)
    const int half = w & 1;      // v-half this warp covers

    const uint64_t NEG1 = 0xBF800000BF800000ULL;
    const uint64_t ONE1 = 0x3F8000003F800000ULL;

    // ---- stage 2 rows with 64 threads each ----
    {
        const int rr = tid >> 6;         // staging row
        const int i  = tid & 63;         // entry index
        const ulonglong2* prow =
            reinterpret_cast<const ulonglong2*>(pred) + (blockIdx.x * 2 + rr) * 64;
        const ulonglong2* grow =
            reinterpret_cast<const ulonglong2*>(gt)   + (blockIdx.x * 2 + rr) * 64;
        ulonglong2 r = prow[i];
        const int j = i >> 1;
        if (i & 1) { sB[rr][j] = r; sB[rr][j + 32] = r; }
        else       { sA[rr][j] = r; sA[rr][j + 32] = r; }
        if (i < 4) {   // e_{128+i} = e_i
            if (i & 1) sB[rr][64 + (i >> 1)] = r;
            else       sA[rr][64 + (i >> 1)] = r;
        }
        sg[rr][i] = grow[i];
    }
    __syncthreads();

    // ---- main loop: 16 iters x 4 v's, window = entries k0+2m .. k0+2m+3 ----
    uint64_t a0 = 0, a1 = 0, a2 = 0, a3 = 0;
    const int boff = lane + 16 * half;   // index into sA/sB
    ulonglong2 Fa = sA[rl][boff];
    ulonglong2 Fb = sB[rl][boff];
    ulonglong2 Fc = sA[rl][boff + 1];
    ulonglong2 Fd = sB[rl][boff + 1];
    const ulonglong2* gp = sg[rl] + 32 * half;

    #pragma unroll 4
    for (int m = 0; m < 16; m++) {
        ulonglong2 G0 = gp[2 * m];
        ulonglong2 G1 = gp[2 * m + 1];
        // v+0: positions k..k+3
        ACC(Fa.x, G0.x, a0); ACC(Fa.y, G0.x, a1); ACC(Fb.x, G0.x, a2); ACC(Fb.y, G0.x, a3);
        // v+1
        ACC(Fa.y, G0.y, a0); ACC(Fb.x, G0.y, a1); ACC(Fb.y, G0.y, a2); ACC(Fc.x, G0.y, a3);
        // v+2
        ACC(Fb.x, G1.x, a0); ACC(Fb.y, G1.x, a1); ACC(Fc.x, G1.x, a2); ACC(Fc.y, G1.x, a3);
        // v+3
        ACC(Fb.y, G1.y, a0); ACC(Fc.x, G1.y, a1); ACC(Fc.y, G1.y, a2); ACC(Fd.x, G1.y, a3);
        // slide window by 2 entries; loads contiguous across lanes (16B/lane)
        Fa = Fc; Fb = Fd;
        Fc = sA[rl][boff + m + 2];
        Fd = sB[rl][boff + m + 2];
    }

    // ---- per-(thread,shift) partial sums -> smem ----
    float s0 = __uint_as_float((uint32_t)a0) + __uint_as_float((uint32_t)(a0 >> 32));
    float s1 = __uint_as_float((uint32_t)a1) + __uint_as_float((uint32_t)(a1 >> 32));
    float s2 = __uint_as_float((uint32_t)a2) + __uint_as_float((uint32_t)(a2 >> 32));
    float s3 = __uint_as_float((uint32_t)a3) + __uint_as_float((uint32_t)(a3 >> 32));
    ssum[w][lane] = make_float4(s0, s1, s2, s3);
    __syncthreads();

    // ---- combine v-halves, row min (warps 0,1 each handle one row) ----
    if (w < 2) {
        float4 x = ssum[2 * w][lane];
        float4 y = ssum[2 * w + 1][lane];
        float t0 = x.x + y.x, t1 = x.y + y.y, t2 = x.z + y.z, t3 = x.w + y.w;
        float mn = fminf(fminf(t0, t1), fminf(t2, t3));
        #pragma unroll
        for (int off = 16; off > 0; off >>= 1)
            mn = fminf(mn, __shfl_xor_sync(0xffffffffu, mn, off));
        if (lane == 0) s_rowmin[w] = mn;
    }
    __syncthreads();

    // ---- CTA partial + last-CTA ticket reduction ----
    if (tid == 0) {
        g_partial[blockIdx.x] = s_rowmin[0] + s_rowmin[1];
        __threadfence();
        int ticket = atomicAdd(&g_ctr, 1);
        s_is_last = (ticket == NCTA - 1);
    }
    __syncthreads();

    if (s_is_last) {
        __threadfence();
        float acc = 0.f;
        #pragma unroll
        for (int i = tid; i < NCTA; i += THREADS)
            acc += g_partial[i];
        s_red[tid] = acc;
        __syncthreads();
        #pragma unroll
        for (int off = THREADS / 2; off > 0; off >>= 1) {
            if (tid < off) s_red[tid] += s_red[tid + off];
            __syncthreads();
        }
        if (tid == 0) {
            out[0] = s_red[0] * (1.0f / ((float)NROWS * (float)V));
            g_ctr = 0;  // reset for next graph replay
        }
    }
}

extern "C" void kernel_launch(void* const* d_in, const int* in_sizes, int n_in,
                              void* d_out, int out_size)
{
    const float* pred = (const float*)d_in[0];
    const float* gt   = (const float*)d_in[1];
    polyloss_kernel<<<NCTA, THREADS>>>(pred, gt, (float*)d_out);
}

// round 5
// speedup vs baseline: 1.0156x; 1.0156x over previous
#include <cuda_runtime.h>
#include <cstdint>

// PolyLoss: N=4096 rows, V=128 circular shifts, last dim = 2 (packed f32x2).
// per_shift[n,s] = (1/V) sum_v |pred[n,(s+v)%V] - gt[n,v]|_1 ; loss = mean_n min_s
//
// 4 rows per 256-thread CTA, 2 warps per row (warp half h covers v in
// [64h,64h+64)). Lane owns shifts 4*lane..4*lane+3 via a sliding register
// window; pred entries (ulonglong2 = 2 packed-f32x2 positions) stored
// even/odd split (sA/sB) so lane loads are 16B-contiguous. Mainloop fully
// unrolled: no MOV slides, no loop overhead, smem at [R+imm].

#define NROWS 4096
#define V 128
#define RPC 4
#define NCTA (NROWS / RPC)    // 1024
#define THREADS 256

__device__ float g_partial[NCTA];
__device__ int g_ctr;

__device__ __forceinline__ uint64_t fma2(uint64_t a, uint64_t b, uint64_t c) {
    uint64_t d;
    asm("fma.rn.f32x2 %0, %1, %2, %3;" : "=l"(d) : "l"(a), "l"(b), "l"(c));
    return d;
}

// acc += | p - g | (componentwise, packed): FFMA2 + 2xLOP3 + FFMA2
#define ACC(p2, g2, acc) do {                      \
    uint64_t _d = fma2((g2), NEG1, (p2));          \
    _d &= 0x7fffffff7fffffffULL;                   \
    (acc) = fma2(_d, ONE1, (acc));                 \
} while (0)

__global__ void __launch_bounds__(THREADS, 5) polyloss_kernel(
    const float* __restrict__ pred, const float* __restrict__ gt,
    float* __restrict__ out)
{
    // Entry e_k holds positions (2k,2k+1), k=0..131, e_{k+64}=e_k (circular).
    // Even entries in sA, odd in sB: e_{2j}=sA[j], e_{2j+1}=sB[j].
    __shared__ ulonglong2 sA[RPC][66];
    __shared__ ulonglong2 sB[RPC][66];
    __shared__ ulonglong2 sg[RPC][64];
    __shared__ float4 ssum[2 * RPC][32];
    __shared__ float s_rowmin[RPC];
    __shared__ int s_is_last;
    __shared__ float s_red[THREADS];

    const int tid  = threadIdx.x;
    const int w    = tid >> 5;          // 0..7
    const int lane = tid & 31;
    const int rl   = w >> 1;            // row within CTA (0..3)
    const int half = w & 1;             // v-half this warp covers

    const uint64_t NEG1 = 0xBF800000BF800000ULL;
    const uint64_t ONE1 = 0x3F8000003F800000ULL;

    // ---- stage 4 rows, 64 threads each (threads 64r..64r+63 stage row r,
    //      which is consumed exactly by warps 2r,2r+1 = those same threads) ----
    {
        const int rr = tid >> 6;
        const int i  = tid & 63;
        const ulonglong2* prow =
            reinterpret_cast<const ulonglong2*>(pred) + (blockIdx.x * RPC + rr) * 64;
        const ulonglong2* grow =
            reinterpret_cast<const ulonglong2*>(gt)   + (blockIdx.x * RPC + rr) * 64;
        ulonglong2 r = prow[i];
        const int j = i >> 1;
        if (i & 1) { sB[rr][j] = r; sB[rr][j + 32] = r; }
        else       { sA[rr][j] = r; sA[rr][j + 32] = r; }
        if (i < 4) {
            if (i & 1) sB[rr][64 + (i >> 1)] = r;
            else       sA[rr][64 + (i >> 1)] = r;
        }
        sg[rr][i] = grow[i];
    }
    // 64-thread named barrier per row group (ids 1..4; issued by all threads,
    // uniform within each group)
    asm volatile("bar.sync %0, 64;" :: "r"(1 + rl) : "memory");

    // ---- mainloop: fully unrolled 16 blocks x 4 v's ----
    uint64_t a0 = 0, a1 = 0, a2 = 0, a3 = 0;
    const int boff = lane + 16 * half;
    const ulonglong2* Ap = sA[rl];
    const ulonglong2* Bp = sB[rl];
    const ulonglong2* gp = sg[rl] + 32 * half;

    ulonglong2 Fa = Ap[boff];
    ulonglong2 Fb = Bp[boff];
    ulonglong2 Fc = Ap[boff + 1];
    ulonglong2 Fd = Bp[boff + 1];

    #pragma unroll
    for (int m = 0; m < 16; m++) {
        ulonglong2 G0 = gp[2 * m];
        ulonglong2 G1 = gp[2 * m + 1];
        // v+0: positions k..k+3
        ACC(Fa.x, G0.x, a0); ACC(Fa.y, G0.x, a1); ACC(Fb.x, G0.x, a2); ACC(Fb.y, G0.x, a3);
        // v+1
        ACC(Fa.y, G0.y, a0); ACC(Fb.x, G0.y, a1); ACC(Fb.y, G0.y, a2); ACC(Fc.x, G0.y, a3);
        // v+2
        ACC(Fb.x, G1.x, a0); ACC(Fb.y, G1.x, a1); ACC(Fc.x, G1.x, a2); ACC(Fc.y, G1.x, a3);
        // v+3
        ACC(Fb.y, G1.y, a0); ACC(Fc.x, G1.y, a1); ACC(Fc.y, G1.y, a2); ACC(Fd.x, G1.y, a3);
        // slide: with full unroll these are register renames, not MOVs
        Fa = Fc; Fb = Fd;
        Fc = Ap[boff + m + 2];
        Fd = Bp[boff + m + 2];
    }

    // ---- per-(thread,shift) partials -> smem ----
    float s0 = __uint_as_float((uint32_t)a0) + __uint_as_float((uint32_t)(a0 >> 32));
    float s1 = __uint_as_float((uint32_t)a1) + __uint_as_float((uint32_t)(a1 >> 32));
    float s2 = __uint_as_float((uint32_t)a2) + __uint_as_float((uint32_t)(a2 >> 32));
    float s3 = __uint_as_float((uint32_t)a3) + __uint_as_float((uint32_t)(a3 >> 32));
    ssum[w][lane] = make_float4(s0, s1, s2, s3);
    __syncthreads();

    // ---- combine v-halves + row min: warp r handles row r ----
    if (w < RPC) {
        float4 x = ssum[2 * w][lane];
        float4 y = ssum[2 * w + 1][lane];
        float t0 = x.x + y.x, t1 = x.y + y.y, t2 = x.z + y.z, t3 = x.w + y.w;
        float mn = fminf(fminf(t0, t1), fminf(t2, t3));
        #pragma unroll
        for (int off = 16; off > 0; off >>= 1)
            mn = fminf(mn, __shfl_xor_sync(0xffffffffu, mn, off));
        if (lane == 0) s_rowmin[w] = mn;
    }
    __syncthreads();

    // ---- CTA partial + last-CTA ticket reduction ----
    if (tid == 0) {
        g_partial[blockIdx.x] =
            (s_rowmin[0] + s_rowmin[1]) + (s_rowmin[2] + s_rowmin[3]);
        __threadfence();
        int ticket = atomicAdd(&g_ctr, 1);
        s_is_last = (ticket == NCTA - 1);
    }
    __syncthreads();

    if (s_is_last) {
        __threadfence();
        float acc = 0.f;
        #pragma unroll
        for (int i = tid; i < NCTA; i += THREADS)
            acc += g_partial[i];
        s_red[tid] = acc;
        __syncthreads();
        #pragma unroll
        for (int off = THREADS / 2; off > 0; off >>= 1) {
            if (tid < off) s_red[tid] += s_red[tid + off];
            __syncthreads();
        }
        if (tid == 0) {
            out[0] = s_red[0] * (1.0f / ((float)NROWS * (float)V));
            g_ctr = 0;  // reset for next graph replay
        }
    }
}

extern "C" void kernel_launch(void* const* d_in, const int* in_sizes, int n_in,
                              void* d_out, int out_size)
{
    const float* pred = (const float*)d_in[0];
    const float* gt   = (const float*)d_in[1];
    polyloss_kernel<<<NCTA, THREADS>>>(pred, gt, (float*)d_out);
}